// round 11
// baseline (speedup 1.0000x reference)
#include <cuda_runtime.h>
#include <cstdint>

// SGNN projection, GB300 sm_103a.
//
// per partition p, row b, seed h:
//   v = (sig*seed) mod M, M = 2^31-1 ; center: v>HALF -> v-M ; mean over valid m ; /HALF
//
// Mersenne modulus with seed-doubling: sd2 = 2*seed, p2 = x*sd2.
//   p2.hi = (x*seed)>>31 ; p2.lo = 2*((x*seed) mod 2^31)
//   s = (p2.lo>>1) + p2.hi <= 2^32-3 < 2M ; v = umin(s, s-M) = umin(s, s+0x80000001)
// Centered sum = sum(v) - M*count(bit30(v)).
//
// Launch: grid (1024 rows, 3 seed-slices) x 224 threads. 4 CTAs/SM (28 warps)
// and a ~73-reg budget so ptxas can pipeline the LDS.128 -> compute blocks.
//
// Input dtypes runtime-detected (int64 vs int32 sig/seed; u8/i32/f32 mask):
// int64-encoded values < 2^31 have all-zero odd 32-bit words.

#define BUCKETS_U 2147483647u
#define HALF_F    1073741823.0f

__device__ __forceinline__ void step(unsigned int x, unsigned int sd2,
                                     unsigned long long& acc, unsigned int& nhi)
{
    const unsigned long long p2 = (unsigned long long)x * sd2;   // IMAD.WIDE.U32
    const unsigned int plo = (unsigned int)p2;
    const unsigned int phi = (unsigned int)(p2 >> 32);
    const unsigned int s   = (plo >> 1) + phi;                   // SHF+IADD / LEA
    const unsigned int v   = umin(s, s + 0x80000001u);           // IADD3 + IMNMX
    acc += (unsigned long long)v;
    nhi += (v >> 30);
}

__global__ __launch_bounds__(224, 4)
void sgnn_project_kernel(const void* __restrict__ sig_raw,   // [3,1024,128]
                         const void* __restrict__ mask_raw,  // [3,1024,128]
                         const void* __restrict__ seed_raw,  // [672]
                         float* __restrict__ out)            // [1024, 672] f32
{
    __shared__ __align__(16) unsigned int s_sig[3][144];  // compacted sigs, padded to x16
    __shared__ int s_cnt[3];
    __shared__ int s_sig64, s_seed64, s_maskmode;

    const int b   = blockIdx.x;
    const int tid = threadIdx.x;

    if (tid < 3) s_cnt[tid] = 0;

    if (tid == 0) {
        // --- dtype detection (deterministic, data-driven) ---
        const unsigned int* s32 = (const unsigned int*)sig_raw;
        unsigned int orh = 0;
#pragma unroll
        for (int k = 0; k < 16; ++k) orh |= s32[2 * k + 1];
        s_sig64 = (orh == 0u);   // int64 little-endian: odd words are zero

        const unsigned int* d32 = (const unsigned int*)seed_raw;
        unsigned int orh2 = 0;
#pragma unroll
        for (int k = 0; k < 16; ++k) orh2 |= d32[2 * k + 1];
        s_seed64 = (orh2 == 0u);

        const unsigned char* m8 = (const unsigned char*)mask_raw;
        unsigned int or12 = 0, or3 = 0;
#pragma unroll
        for (int k = 0; k < 32; ++k) {
            or12 |= (unsigned int)m8[4 * k + 1] | (unsigned int)m8[4 * k + 2];
            or3  |= (unsigned int)m8[4 * k + 3];
        }
        int mode;
        if (or12 == 0u && or3 == 0u)                      mode = 1;  // int32 {0,1}
        else if (or12 == 0u && (or3 & ~0x3Fu) == 0u)      mode = 2;  // float32 {0.0f,1.0f}
        else                                              mode = 0;  // uint8 bool
        s_maskmode = mode;
    }
    __syncthreads();

    const int sig64    = s_sig64;
    const int seed64   = s_seed64;
    const int maskmode = s_maskmode;

    // --- cooperative masked compaction: 3 partitions x 128 slots, 224 threads ---
    for (int t = tid; t < 384; t += 224) {
        const int p = t >> 7;
        const int m = t & 127;
        const size_t idx = ((size_t)p * 1024 + (size_t)b) * 128 + (size_t)m;

        bool valid;
        if (maskmode == 0)      valid = ((const unsigned char*)mask_raw)[idx] != 0;
        else if (maskmode == 1) valid = ((const int*)mask_raw)[idx] != 0;
        else                    valid = ((const float*)mask_raw)[idx] != 0.0f;

        if (valid) {
            const unsigned int* s32 = (const unsigned int*)sig_raw;
            const unsigned int v = sig64 ? s32[2 * idx] : s32[idx];  // low word; value < 2^31
            const int pos = atomicAdd(&s_cnt[p], 1);
            s_sig[p][pos] = v;
        }
    }
    __syncthreads();

    // --- pad each partition to a multiple of 16 with zeros (zero contributes nothing) ---
    if (tid < 3) {
        const int c  = s_cnt[tid];
        const int cp = (c + 15) & ~15;
        for (int k = c; k < cp; ++k) s_sig[tid][k] = 0u;
    }
    __syncthreads();

    // --- per-thread: one seed h, loop over compacted sigs of its partition ---
    const int h = blockIdx.y * 224 + tid;                // 0..671
    const int p = (h < 112) ? 0 : ((h < 336) ? 1 : 2);
    const unsigned int* d32 = (const unsigned int*)seed_raw;
    const unsigned int sd  = seed64 ? d32[2 * h] : d32[h];  // seed in [1, 2^31)
    const unsigned int sd2 = sd + sd;
    const int cnt   = s_cnt[p];
    const int niter = ((cnt + 15) & ~15) >> 4;

    unsigned long long acc0 = 0ull, acc1 = 0ull;  // sums of v in [0, M)
    unsigned int nhi0 = 0u, nhi1 = 0u;            // counts of v > HALF

    const uint4* sp = (const uint4*)&s_sig[p][0];  // rows are 576B = 16B-aligned

    for (int it = 0; it < niter; ++it, sp += 4) {
        // batch the 4 broadcast LDS.128 up front; compute block hides their latency
        const uint4 q0 = sp[0];
        const uint4 q1 = sp[1];
        const uint4 q2 = sp[2];
        const uint4 q3 = sp[3];

        step(q0.x, sd2, acc0, nhi0); step(q0.y, sd2, acc1, nhi1);
        step(q0.z, sd2, acc0, nhi0); step(q0.w, sd2, acc1, nhi1);
        step(q1.x, sd2, acc0, nhi0); step(q1.y, sd2, acc1, nhi1);
        step(q1.z, sd2, acc0, nhi0); step(q1.w, sd2, acc1, nhi1);
        step(q2.x, sd2, acc0, nhi0); step(q2.y, sd2, acc1, nhi1);
        step(q2.z, sd2, acc0, nhi0); step(q2.w, sd2, acc1, nhi1);
        step(q3.x, sd2, acc0, nhi0); step(q3.y, sd2, acc1, nhi1);
        step(q3.z, sd2, acc0, nhi0); step(q3.w, sd2, acc1, nhi1);
    }

    const unsigned long long acc = acc0 + acc1;
    const unsigned int nhi = nhi0 + nhi1;
    const long long centered = (long long)acc - (long long)nhi * 2147483647ll;
    const float cntf = (float)(cnt > 0 ? cnt : 1);
    const float mean = (float)centered / cntf;
    out[(size_t)b * 672 + (size_t)h] = mean * (1.0f / HALF_F);
}

extern "C" void kernel_launch(void* const* d_in, const int* in_sizes, int n_in,
                              void* d_out, int out_size)
{
    (void)in_sizes; (void)n_in; (void)out_size;
    dim3 grid(1024, 3);
    sgnn_project_kernel<<<grid, 224>>>(d_in[0], d_in[1], d_in[2], (float*)d_out);
}